// round 7
// baseline (speedup 1.0000x reference)
#include <cuda_runtime.h>
#include <math.h>

#define BATCH 16
#define NPTS  200000
#define SZ    224
#define PIX   (SZ*SZ)
#define EPSF  1e-8f

// ---------------- scratch (static __device__, no allocations) ----------------
__device__ float4   g_acc4[BATCH*PIX];   // per pixel: (wsum, zn*w, nx*w, ny*w)
__device__ float    g_acc1[BATCH*PIX];   // per pixel: nz*w
__device__ unsigned g_mm[BATCH*6];       // per batch: xmin,xmax,ymin,ymax,zmin,zmax (order-encoded)
__device__ float    g_tr[BATCH*6];       // per batch: xmn,invx, ymn,invy, zmn,invz
__device__ unsigned g_cmm[2];            // global combined min,max (order-encoded)

// monotonic float<->uint encoding so atomicMin/Max on unsigned == float min/max
__device__ __forceinline__ unsigned fenc(float f){
    unsigned u = __float_as_uint(f);
    return (u & 0x80000000u) ? ~u : (u | 0x80000000u);
}
__device__ __forceinline__ float fdec(unsigned u){
    return __uint_as_float((u & 0x80000000u) ? (u & 0x7fffffffu) : ~u);
}

// ---------------- kernel 0: zero accumulators, init min/max --------------------
__global__ void k_init(){
    int i = blockIdx.x*blockDim.x + threadIdx.x;
    int stride = gridDim.x*blockDim.x;
    for (int idx = i; idx < BATCH*PIX; idx += stride){
        g_acc4[idx] = make_float4(0.f,0.f,0.f,0.f);
        g_acc1[idx] = 0.f;
    }
    if (i < BATCH*6) g_mm[i] = (i & 1) ? 0u : 0xFFFFFFFFu;  // even=min slot, odd=max slot
    if (i == 0){ g_cmm[0] = 0xFFFFFFFFu; g_cmm[1] = 0u; }
}

// ---------------- kernel 1: per-batch min/max of x,y,z ------------------------
__global__ void k_minmax(const float* __restrict__ pts){
    int b = blockIdx.y;
    const float* p = pts + (size_t)b*NPTS*3;
    float mn0= INFINITY, mn1= INFINITY, mn2= INFINITY;
    float mx0=-INFINITY, mx1=-INFINITY, mx2=-INFINITY;
    for (int i = blockIdx.x*blockDim.x + threadIdx.x; i < NPTS; i += gridDim.x*blockDim.x){
        float v0 = p[3*i+0], v1 = p[3*i+1], v2 = p[3*i+2];
        mn0 = fminf(mn0,v0); mx0 = fmaxf(mx0,v0);
        mn1 = fminf(mn1,v1); mx1 = fmaxf(mx1,v1);
        mn2 = fminf(mn2,v2); mx2 = fmaxf(mx2,v2);
    }
    #pragma unroll
    for (int o = 16; o; o >>= 1){
        mn0 = fminf(mn0, __shfl_xor_sync(0xffffffffu, mn0, o));
        mx0 = fmaxf(mx0, __shfl_xor_sync(0xffffffffu, mx0, o));
        mn1 = fminf(mn1, __shfl_xor_sync(0xffffffffu, mn1, o));
        mx1 = fmaxf(mx1, __shfl_xor_sync(0xffffffffu, mx1, o));
        mn2 = fminf(mn2, __shfl_xor_sync(0xffffffffu, mn2, o));
        mx2 = fmaxf(mx2, __shfl_xor_sync(0xffffffffu, mx2, o));
    }
    __shared__ float smn[8][3], smx[8][3];
    int w = threadIdx.x >> 5, l = threadIdx.x & 31;
    int nw = blockDim.x >> 5;
    if (l == 0){
        smn[w][0]=mn0; smn[w][1]=mn1; smn[w][2]=mn2;
        smx[w][0]=mx0; smx[w][1]=mx1; smx[w][2]=mx2;
    }
    __syncthreads();
    if (threadIdx.x == 0){
        for (int k = 1; k < nw; k++){
            mn0 = fminf(mn0, smn[k][0]); mx0 = fmaxf(mx0, smx[k][0]);
            mn1 = fminf(mn1, smn[k][1]); mx1 = fmaxf(mx1, smx[k][1]);
            mn2 = fminf(mn2, smn[k][2]); mx2 = fmaxf(mx2, smx[k][2]);
        }
        atomicMin(&g_mm[b*6+0], fenc(mn0)); atomicMax(&g_mm[b*6+1], fenc(mx0));
        atomicMin(&g_mm[b*6+2], fenc(mn1)); atomicMax(&g_mm[b*6+3], fenc(mx1));
        atomicMin(&g_mm[b*6+4], fenc(mn2)); atomicMax(&g_mm[b*6+5], fenc(mx2));
    }
}

// ---------------- kernel 1b: per-batch transforms -----------------------------
// XLA algsimp rewrites div(X, broadcast(den)) -> mul(X, broadcast(1/den)):
// one correctly-rounded reciprocal per batch, per-point multiply.
__global__ void k_prep(){
    int b = threadIdx.x;
    if (b >= BATCH) return;
    const unsigned* mm = g_mm + b*6;
    float xmn = fdec(mm[0]), xmx = fdec(mm[1]);
    float ymn = fdec(mm[2]), ymx = fdec(mm[3]);
    float zmn = fdec(mm[4]), zmx = fdec(mm[5]);
    g_tr[b*6+0] = xmn;
    g_tr[b*6+1] = __fdiv_rn(1.f, __fadd_rn(__fsub_rn(xmx, xmn), EPSF));
    g_tr[b*6+2] = ymn;
    g_tr[b*6+3] = __fdiv_rn(1.f, __fadd_rn(__fsub_rn(ymx, ymn), EPSF));
    g_tr[b*6+4] = zmn;
    g_tr[b*6+5] = __fdiv_rn(1.f, __fadd_rn(__fsub_rn(zmx, zmn), EPSF));
}

// ---------------- kernel 2: per-point scatter-add -----------------------------
// fx = rn(rn(rn(x - xmn) * inv) * 223), trunc, clip — the post-rewrite HLO.
__global__ void k_scatter(const float* __restrict__ pts,
                          const float* __restrict__ dens,
                          const float* __restrict__ nrm){
    int idx = blockIdx.x*blockDim.x + threadIdx.x;
    if (idx >= BATCH*NPTS) return;
    int b = idx / NPTS;
    const float* tr = g_tr + b*6;
    float xmn = tr[0], ivx = tr[1];
    float ymn = tr[2], ivy = tr[3];
    float zmn = tr[4], ivz = tr[5];

    float x = pts[3*idx+0], y = pts[3*idx+1], z = pts[3*idx+2];
    float w = __fdiv_rn(1.f, __fadd_rn(1.f, expf(-dens[idx])));

    float fx = __fmul_rn(__fmul_rn(__fsub_rn(x, xmn), ivx), 223.0f);
    float fy = __fmul_rn(__fmul_rn(__fsub_rn(y, ymn), ivy), 223.0f);
    int xp = min(max((int)fx, 0), SZ-1);
    int yp = min(max((int)fy, 0), SZ-1);
    float zn = __fmul_rn(__fsub_rn(z, zmn), ivz);

    float nx = nrm[3*idx+0], ny = nrm[3*idx+1], nz = nrm[3*idx+2];

    int pix = b*PIX + yp*SZ + xp;
    atomicAdd(&g_acc4[pix], make_float4(w, __fmul_rn(zn, w),
                                        __fmul_rn(nx, w), __fmul_rn(ny, w)));
    atomicAdd(&g_acc1[pix], __fmul_rn(nz, w));
}

// ---------------- kernel 3: per-pixel finalize + global min/max ---------------
__global__ void k_final(float* __restrict__ out){
    int idx = blockIdx.x*blockDim.x + threadIdx.x;
    float lmin =  INFINITY, lmax = -INFINITY;
    if (idx < BATCH*PIX){
        float4 a  = g_acc4[idx];
        float anz = g_acc1[idx];
        float safe = (a.x > 0.f) ? a.x : 1.f;
        float depth = __fdiv_rn(a.y, safe);       // invalid pixel: 0/1 == 0, matches ref
        float nx = __fdiv_rn(a.z, safe);
        float ny = __fdiv_rn(a.w, safe);
        float nz = __fdiv_rn(anz, safe);
        float ss = __fadd_rn(__fadd_rn(__fadd_rn(__fmul_rn(nx,nx), __fmul_rn(ny,ny)),
                                       __fmul_rn(nz,nz)), EPSF);
        float rn = __fsqrt_rn(ss);
        float c0 = depth;
        float c1 = __fmul_rn(__fadd_rn(__fdiv_rn(nx, rn), 1.f), 0.5f);
        float c2 = __fmul_rn(__fadd_rn(__fdiv_rn(ny, rn), 1.f), 0.5f);
        int b = idx / PIX, p = idx - b*PIX;
        out[(b*3+0)*PIX + p] = c0;
        out[(b*3+1)*PIX + p] = c1;
        out[(b*3+2)*PIX + p] = c2;
        lmin = fminf(c0, fminf(c1, c2));
        lmax = fmaxf(c0, fmaxf(c1, c2));
    }
    #pragma unroll
    for (int o = 16; o; o >>= 1){
        lmin = fminf(lmin, __shfl_xor_sync(0xffffffffu, lmin, o));
        lmax = fmaxf(lmax, __shfl_xor_sync(0xffffffffu, lmax, o));
    }
    __shared__ float smn[8], smx[8];
    int w = threadIdx.x >> 5, l = threadIdx.x & 31;
    int nw = blockDim.x >> 5;
    if (l == 0){ smn[w] = lmin; smx[w] = lmax; }
    __syncthreads();
    if (threadIdx.x == 0){
        for (int k = 1; k < nw; k++){
            lmin = fminf(lmin, smn[k]);
            lmax = fmaxf(lmax, smx[k]);
        }
        atomicMin(&g_cmm[0], fenc(lmin));
        atomicMax(&g_cmm[1], fenc(lmax));
    }
}

// ---------------- kernel 4: global min-max normalize --------------------------
// Also divide-by-broadcast-scalar in the reference -> recip-multiply form.
__global__ void k_norm(float* __restrict__ out, int n){
    float cmn = fdec(g_cmm[0]);
    float cmx = fdec(g_cmm[1]);
    float inv = __fdiv_rn(1.f, __fadd_rn(__fsub_rn(cmx, cmn), EPSF));
    int i = blockIdx.x*blockDim.x + threadIdx.x;
    if (i < n) out[i] = __fmul_rn(__fsub_rn(out[i], cmn), inv);
}

// ---------------- launch ------------------------------------------------------
extern "C" void kernel_launch(void* const* d_in, const int* in_sizes, int n_in,
                              void* d_out, int out_size){
    const float* pts  = (const float*)d_in[0];   // [16, 200000, 3]
    const float* dens = (const float*)d_in[1];   // [16, 200000, 1]
    const float* nrm  = (const float*)d_in[2];   // [16, 200000, 3]
    float* out = (float*)d_out;                  // [16, 3, 224, 224]

    k_init<<<2048, 256>>>();
    k_minmax<<<dim3(96, BATCH), 256>>>(pts);
    k_prep<<<1, 32>>>();
    k_scatter<<<(BATCH*NPTS + 255)/256, 256>>>(pts, dens, nrm);
    k_final<<<(BATCH*PIX + 255)/256, 256>>>(out);
    k_norm<<<(3*BATCH*PIX + 255)/256, 256>>>(out, 3*BATCH*PIX);
}

// round 10
// speedup vs baseline: 1.0930x; 1.0930x over previous
#include <cuda_runtime.h>
#include <math.h>

#define BATCH 16
#define NPTS  200000
#define NG    (NPTS/4)          // point-groups per batch (4 pts/group)
#define SZ    224
#define PIX   (SZ*SZ)
#define EPSF  1e-8f

// ---------------- scratch (static __device__, no allocations) ----------------
__device__ float4   g_acc4[BATCH*PIX];   // per pixel: (wsum, zn*w, nx*w, ny*w)
__device__ float    g_acc1[BATCH*PIX];   // per pixel: nz*w
__device__ unsigned g_mm[BATCH*6];       // per batch: xmin,xmax,ymin,ymax,zmin,zmax (order-encoded)
__device__ float    g_tr[BATCH*6];       // per batch: xmn,invx, ymn,invy, zmn,invz
__device__ unsigned g_cmm[2];            // global combined min,max (order-encoded)

// monotonic float<->uint encoding so atomicMin/Max on unsigned == float min/max
__device__ __forceinline__ unsigned fenc(float f){
    unsigned u = __float_as_uint(f);
    return (u & 0x80000000u) ? ~u : (u | 0x80000000u);
}
__device__ __forceinline__ float fdec(unsigned u){
    return __uint_as_float((u & 0x80000000u) ? (u & 0x7fffffffu) : ~u);
}

// ---------------- kernel 0: zero accumulators, init min/max --------------------
__global__ void k_init(){
    int i = blockIdx.x*blockDim.x + threadIdx.x;
    int stride = gridDim.x*blockDim.x;
    for (int idx = i; idx < BATCH*PIX; idx += stride){
        g_acc4[idx] = make_float4(0.f,0.f,0.f,0.f);
        g_acc1[idx] = 0.f;
    }
    if (i < BATCH*6) g_mm[i] = (i & 1) ? 0u : 0xFFFFFFFFu;  // even=min slot, odd=max slot
    if (i == 0){ g_cmm[0] = 0xFFFFFFFFu; g_cmm[1] = 0u; }
}

// ---------------- kernel 1: per-batch min/max of x,y,z (float4 loads) ---------
__global__ void k_minmax(const float4* __restrict__ pts4){
    int b = blockIdx.y;
    const float4* p = pts4 + (size_t)b*NG*3;
    float mn0= INFINITY, mn1= INFINITY, mn2= INFINITY;
    float mx0=-INFINITY, mx1=-INFINITY, mx2=-INFINITY;
    for (int g = blockIdx.x*blockDim.x + threadIdx.x; g < NG; g += gridDim.x*blockDim.x){
        float4 a = p[3*g+0];           // x0 y0 z0 x1
        float4 c = p[3*g+1];           // y1 z1 x2 y2
        float4 d = p[3*g+2];           // z2 x3 y3 z3
        float xlo = fminf(fminf(a.x, a.w), fminf(c.z, d.y));
        float xhi = fmaxf(fmaxf(a.x, a.w), fmaxf(c.z, d.y));
        float ylo = fminf(fminf(a.y, c.x), fminf(c.w, d.z));
        float yhi = fmaxf(fmaxf(a.y, c.x), fmaxf(c.w, d.z));
        float zlo = fminf(fminf(a.z, c.y), fminf(d.x, d.w));
        float zhi = fmaxf(fmaxf(a.z, c.y), fmaxf(d.x, d.w));
        mn0 = fminf(mn0, xlo); mx0 = fmaxf(mx0, xhi);
        mn1 = fminf(mn1, ylo); mx1 = fmaxf(mx1, yhi);
        mn2 = fminf(mn2, zlo); mx2 = fmaxf(mx2, zhi);
    }
    #pragma unroll
    for (int o = 16; o; o >>= 1){
        mn0 = fminf(mn0, __shfl_xor_sync(0xffffffffu, mn0, o));
        mx0 = fmaxf(mx0, __shfl_xor_sync(0xffffffffu, mx0, o));
        mn1 = fminf(mn1, __shfl_xor_sync(0xffffffffu, mn1, o));
        mx1 = fmaxf(mx1, __shfl_xor_sync(0xffffffffu, mx1, o));
        mn2 = fminf(mn2, __shfl_xor_sync(0xffffffffu, mn2, o));
        mx2 = fmaxf(mx2, __shfl_xor_sync(0xffffffffu, mx2, o));
    }
    __shared__ float smn[8][3], smx[8][3];
    int w = threadIdx.x >> 5, l = threadIdx.x & 31;
    int nw = blockDim.x >> 5;
    if (l == 0){
        smn[w][0]=mn0; smn[w][1]=mn1; smn[w][2]=mn2;
        smx[w][0]=mx0; smx[w][1]=mx1; smx[w][2]=mx2;
    }
    __syncthreads();
    if (threadIdx.x == 0){
        for (int k = 1; k < nw; k++){
            mn0 = fminf(mn0, smn[k][0]); mx0 = fmaxf(mx0, smx[k][0]);
            mn1 = fminf(mn1, smn[k][1]); mx1 = fmaxf(mx1, smx[k][1]);
            mn2 = fminf(mn2, smn[k][2]); mx2 = fmaxf(mx2, smx[k][2]);
        }
        atomicMin(&g_mm[b*6+0], fenc(mn0)); atomicMax(&g_mm[b*6+1], fenc(mx0));
        atomicMin(&g_mm[b*6+2], fenc(mn1)); atomicMax(&g_mm[b*6+3], fenc(mx1));
        atomicMin(&g_mm[b*6+4], fenc(mn2)); atomicMax(&g_mm[b*6+5], fenc(mx2));
    }
}

// ---------------- kernel 1b: per-batch transforms -----------------------------
// XLA algsimp: div(X, broadcast(den)) -> mul(X, broadcast(1/den)).
__global__ void k_prep(){
    int b = threadIdx.x;
    if (b >= BATCH) return;
    const unsigned* mm = g_mm + b*6;
    float xmn = fdec(mm[0]), xmx = fdec(mm[1]);
    float ymn = fdec(mm[2]), ymx = fdec(mm[3]);
    float zmn = fdec(mm[4]), zmx = fdec(mm[5]);
    g_tr[b*6+0] = xmn;
    g_tr[b*6+1] = __fdiv_rn(1.f, __fadd_rn(__fsub_rn(xmx, xmn), EPSF));
    g_tr[b*6+2] = ymn;
    g_tr[b*6+3] = __fdiv_rn(1.f, __fadd_rn(__fsub_rn(ymx, ymn), EPSF));
    g_tr[b*6+4] = zmn;
    g_tr[b*6+5] = __fdiv_rn(1.f, __fadd_rn(__fsub_rn(zmx, zmn), EPSF));
}

// ---------------- kernel 2: scatter-add, 4 points/thread, LDG.128 -------------
__device__ __forceinline__ void scatter_pt(
    float x, float y, float z, float d, float nx, float ny, float nz,
    float xmn, float ivx, float ymn, float ivy, float zmn, float ivz, int base)
{
    float w = __fdiv_rn(1.f, __fadd_rn(1.f, expf(-d)));
    float fx = __fmul_rn(__fmul_rn(__fsub_rn(x, xmn), ivx), 223.0f);
    float fy = __fmul_rn(__fmul_rn(__fsub_rn(y, ymn), ivy), 223.0f);
    int xp = min(max((int)fx, 0), SZ-1);
    int yp = min(max((int)fy, 0), SZ-1);
    float zn = __fmul_rn(__fsub_rn(z, zmn), ivz);
    int pix = base + yp*SZ + xp;
    atomicAdd(&g_acc4[pix], make_float4(w, __fmul_rn(zn, w),
                                        __fmul_rn(nx, w), __fmul_rn(ny, w)));
    atomicAdd(&g_acc1[pix], __fmul_rn(nz, w));
}

__global__ void k_scatter(const float4* __restrict__ pts4,
                          const float4* __restrict__ dens4,
                          const float4* __restrict__ nrm4){
    int g = blockIdx.x*blockDim.x + threadIdx.x;   // group of 4 points
    if (g >= BATCH*NG) return;
    int b = g / NG;                                 // NPTS%4==0: no straddle
    const float* tr = g_tr + b*6;
    float xmn = tr[0], ivx = tr[1];
    float ymn = tr[2], ivy = tr[3];
    float zmn = tr[4], ivz = tr[5];
    int base = b*PIX;

    float4 p0 = pts4[3*g+0];   // x0 y0 z0 x1
    float4 p1 = pts4[3*g+1];   // y1 z1 x2 y2
    float4 p2 = pts4[3*g+2];   // z2 x3 y3 z3
    float4 dd = dens4[g];
    float4 n0 = nrm4[3*g+0];
    float4 n1 = nrm4[3*g+1];
    float4 n2 = nrm4[3*g+2];

    scatter_pt(p0.x, p0.y, p0.z, dd.x, n0.x, n0.y, n0.z, xmn,ivx,ymn,ivy,zmn,ivz, base);
    scatter_pt(p0.w, p1.x, p1.y, dd.y, n0.w, n1.x, n1.y, xmn,ivx,ymn,ivy,zmn,ivz, base);
    scatter_pt(p1.z, p1.w, p2.x, dd.z, n1.z, n1.w, n2.x, xmn,ivx,ymn,ivy,zmn,ivz, base);
    scatter_pt(p2.y, p2.z, p2.w, dd.w, n2.y, n2.z, n2.w, xmn,ivx,ymn,ivy,zmn,ivz, base);
}

// ---------------- kernel 3: per-pixel finalize + global min/max ---------------
__global__ void k_final(float* __restrict__ out){
    int idx = blockIdx.x*blockDim.x + threadIdx.x;
    float lmin =  INFINITY, lmax = -INFINITY;
    if (idx < BATCH*PIX){
        float4 a  = g_acc4[idx];
        float anz = g_acc1[idx];
        float safe = (a.x > 0.f) ? a.x : 1.f;
        float depth = __fdiv_rn(a.y, safe);       // invalid pixel: 0/1 == 0, matches ref
        float nx = __fdiv_rn(a.z, safe);
        float ny = __fdiv_rn(a.w, safe);
        float nz = __fdiv_rn(anz, safe);
        float ss = __fadd_rn(__fadd_rn(__fadd_rn(__fmul_rn(nx,nx), __fmul_rn(ny,ny)),
                                       __fmul_rn(nz,nz)), EPSF);
        float rn = __fsqrt_rn(ss);
        float c0 = depth;
        float c1 = __fmul_rn(__fadd_rn(__fdiv_rn(nx, rn), 1.f), 0.5f);
        float c2 = __fmul_rn(__fadd_rn(__fdiv_rn(ny, rn), 1.f), 0.5f);
        int b = idx / PIX, p = idx - b*PIX;
        out[(b*3+0)*PIX + p] = c0;
        out[(b*3+1)*PIX + p] = c1;
        out[(b*3+2)*PIX + p] = c2;
        lmin = fminf(c0, fminf(c1, c2));
        lmax = fmaxf(c0, fmaxf(c1, c2));
    }
    #pragma unroll
    for (int o = 16; o; o >>= 1){
        lmin = fminf(lmin, __shfl_xor_sync(0xffffffffu, lmin, o));
        lmax = fmaxf(lmax, __shfl_xor_sync(0xffffffffu, lmax, o));
    }
    __shared__ float smn[8], smx[8];
    int w = threadIdx.x >> 5, l = threadIdx.x & 31;
    int nw = blockDim.x >> 5;
    if (l == 0){ smn[w] = lmin; smx[w] = lmax; }
    __syncthreads();
    if (threadIdx.x == 0){
        for (int k = 1; k < nw; k++){
            lmin = fminf(lmin, smn[k]);
            lmax = fmaxf(lmax, smx[k]);
        }
        atomicMin(&g_cmm[0], fenc(lmin));
        atomicMax(&g_cmm[1], fenc(lmax));
    }
}

// ---------------- kernel 4: global min-max normalize --------------------------
__global__ void k_norm(float* __restrict__ out, int n){
    float cmn = fdec(g_cmm[0]);
    float cmx = fdec(g_cmm[1]);
    float inv = __fdiv_rn(1.f, __fadd_rn(__fsub_rn(cmx, cmn), EPSF));
    int i = blockIdx.x*blockDim.x + threadIdx.x;
    if (i < n) out[i] = __fmul_rn(__fsub_rn(out[i], cmn), inv);
}

// ---------------- launch ------------------------------------------------------
extern "C" void kernel_launch(void* const* d_in, const int* in_sizes, int n_in,
                              void* d_out, int out_size){
    const float4* pts4  = (const float4*)d_in[0];   // [16, 200000, 3] as float4 groups
    const float4* dens4 = (const float4*)d_in[1];   // [16, 200000, 1]
    const float4* nrm4  = (const float4*)d_in[2];   // [16, 200000, 3]
    float* out = (float*)d_out;                     // [16, 3, 224, 224]

    k_init<<<2048, 256>>>();
    k_minmax<<<dim3(48, BATCH), 256>>>(pts4);
    k_prep<<<1, 32>>>();
    k_scatter<<<(BATCH*NG + 255)/256, 256>>>(pts4, dens4, nrm4);
    k_final<<<(BATCH*PIX + 255)/256, 256>>>(out);
    k_norm<<<(3*BATCH*PIX + 255)/256, 256>>>(out, 3*BATCH*PIX);
}